// round 6
// baseline (speedup 1.0000x reference)
#include <cuda_runtime.h>

// Problem constants (shapes are fixed by the dataset).
#define N_ATOMS_C 20000
#define CAP 96          // per-atom bucket capacity; dataset max degree ~60
#define OVF_CAP 8192
#define MP_SCALING 0.1f

// Scratch: __device__ globals (no allocations allowed; zero-initialized at
// module load). Invariant: g_count/g_ovf_count are 0 on entry to
// kernel_launch and restored to 0 by gather_kernel, so every call does
// identical work.
__device__ int  g_count[N_ATOMS_C];
__device__ int2 g_bucket[N_ATOMS_C * CAP];   // (edge_id, neighbor_id)
__device__ int  g_ovf_count;
__device__ int  g_ovf[OVF_CAP];

__device__ __forceinline__ void scatter_one(int e, int c, int n) {
    int pos = atomicAdd(&g_count[c], 1);
    if (pos < CAP) {
        g_bucket[c * CAP + pos] = make_int2(e, n);
    } else {
        int o = atomicAdd(&g_ovf_count, 1);
        if (o < OVF_CAP) g_ovf[o] = e;
    }
}

__global__ void scatter_kernel(const int* __restrict__ centers,
                               const int* __restrict__ neighbors, int E) {
    int t = blockIdx.x * blockDim.x + threadIdx.x;
    int e = t * 2;
    if (e + 1 < E) {
        int2 c = *(const int2*)(centers + e);
        int2 n = *(const int2*)(neighbors + e);
        scatter_one(e,     c.x, n.x);
        scatter_one(e + 1, c.y, n.y);
    } else if (e < E) {
        scatter_one(e, centers[e], neighbors[e]);
    }
}

// Single-edge accumulate (tail / overflow path).
__device__ __forceinline__ void edge_accum(
    float acc[16], int k,
    const float* __restrict__ sh,
    const float* __restrict__ rb,
    const float* __restrict__ emb,
    int e, int n)
{
    const float* rbe = rb + (size_t)e * 128 + k;
    float r0 = __ldcs(rbe), r1 = __ldcs(rbe + 32), r2 = __ldcs(rbe + 64), r3 = __ldcs(rbe + 96);
    float em = __ldg(emb + (size_t)n * 32 + k);
    float sv = (k < 16) ? __ldcs(sh + (size_t)e * 16 + k) : 0.0f;
    float t0 = r0 * em, t1 = r1 * em, t2 = r2 * em, t3 = r3 * em;
#pragma unroll
    for (int m = 0; m < 16; m++) {
        float s = __shfl_sync(0xffffffffu, sv, m);
        float t = (m < 1) ? t0 : (m < 4) ? t1 : (m < 9) ? t2 : t3;
        acc[m] = fmaf(s, t, acc[m]);
    }
}

// Process up to 32 edges whose (edge,neighbor) pairs live in breg across the
// warp's lanes (lane j holds edge j of this chunk). Edge ids come via shfl,
// so no iteration starts with a dependent memory load.
__device__ __forceinline__ void chunk_accum(
    float acc[16], int k, int cnt, int2 breg,
    const float* __restrict__ sh,
    const float* __restrict__ rb,
    const float* __restrict__ emb)
{
    int i = 0;
    for (; i + 4 <= cnt; i += 4) {
        int e0 = __shfl_sync(0xffffffffu, breg.x, i);
        int n0 = __shfl_sync(0xffffffffu, breg.y, i);
        int e1 = __shfl_sync(0xffffffffu, breg.x, i + 1);
        int n1 = __shfl_sync(0xffffffffu, breg.y, i + 1);
        int e2 = __shfl_sync(0xffffffffu, breg.x, i + 2);
        int n2 = __shfl_sync(0xffffffffu, breg.y, i + 2);
        int e3 = __shfl_sync(0xffffffffu, breg.x, i + 3);
        int n3 = __shfl_sync(0xffffffffu, breg.y, i + 3);

        // ---- front-batched load phase (22 independent LDGs) ----
        const float* p0 = rb + (size_t)e0 * 128 + k;
        const float* p1 = rb + (size_t)e1 * 128 + k;
        const float* p2 = rb + (size_t)e2 * 128 + k;
        const float* p3 = rb + (size_t)e3 * 128 + k;
        float r00=__ldcs(p0), r01=__ldcs(p0+32), r02=__ldcs(p0+64), r03=__ldcs(p0+96);
        float r10=__ldcs(p1), r11=__ldcs(p1+32), r12=__ldcs(p1+64), r13=__ldcs(p1+96);
        float r20=__ldcs(p2), r21=__ldcs(p2+32), r22=__ldcs(p2+64), r23=__ldcs(p2+96);
        float r30=__ldcs(p3), r31=__ldcs(p3+32), r32=__ldcs(p3+64), r33=__ldcs(p3+96);
        float em0 = __ldg(emb + (size_t)n0 * 32 + k);
        float em1 = __ldg(emb + (size_t)n1 * 32 + k);
        float em2 = __ldg(emb + (size_t)n2 * 32 + k);
        float em3 = __ldg(emb + (size_t)n3 * 32 + k);
        float svA = __ldcs(sh + ((k < 16) ? (size_t)e0 * 16 + k
                                          : (size_t)e1 * 16 + (k - 16)));
        float svB = __ldcs(sh + ((k < 16) ? (size_t)e2 * 16 + k
                                          : (size_t)e3 * 16 + (k - 16)));

        // ---- compute phase ----
        float t00=r00*em0, t01=r01*em0, t02=r02*em0, t03=r03*em0;
        float t10=r10*em1, t11=r11*em1, t12=r12*em1, t13=r13*em1;
        float t20=r20*em2, t21=r21*em2, t22=r22*em2, t23=r23*em2;
        float t30=r30*em3, t31=r31*em3, t32=r32*em3, t33=r33*em3;
#pragma unroll
        for (int m = 0; m < 16; m++) {
            float s0 = __shfl_sync(0xffffffffu, svA, m);
            float s1 = __shfl_sync(0xffffffffu, svA, m + 16);
            float s2 = __shfl_sync(0xffffffffu, svB, m);
            float s3 = __shfl_sync(0xffffffffu, svB, m + 16);
            float u0 = (m < 1) ? t00 : (m < 4) ? t01 : (m < 9) ? t02 : t03;
            float u1 = (m < 1) ? t10 : (m < 4) ? t11 : (m < 9) ? t12 : t13;
            float u2 = (m < 1) ? t20 : (m < 4) ? t21 : (m < 9) ? t22 : t23;
            float u3 = (m < 1) ? t30 : (m < 4) ? t31 : (m < 9) ? t32 : t33;
            acc[m] = fmaf(s0, u0, acc[m]);
            acc[m] = fmaf(s1, u1, acc[m]);
            acc[m] = fmaf(s2, u2, acc[m]);
            acc[m] = fmaf(s3, u3, acc[m]);
        }
    }
    for (; i < cnt; i++) {
        int e = __shfl_sync(0xffffffffu, breg.x, i);
        int n = __shfl_sync(0xffffffffu, breg.y, i);
        edge_accum(acc, k, sh, rb, emb, e, n);
    }
}

// One warp per atom; lane = k. The atom's bucket (<=96 entries) is loaded
// into 3 lane-registers up front (3 coalesced 256B loads), removing the
// bucket load from every iteration's critical path.
__global__ __launch_bounds__(128) void gather_kernel(
    const float* __restrict__ sh, const float* __restrict__ rb,
    const float* __restrict__ emb,
    const int* __restrict__ centers, const int* __restrict__ neighbors,
    float* __restrict__ out, int n_atoms)
{
    int a = blockIdx.x * 4 + (threadIdx.x >> 5);
    if (a >= n_atoms) return;
    int k = threadIdx.x & 31;

    int deg_raw = g_count[a];
    int deg = deg_raw > CAP ? CAP : deg_raw;

    float acc[16];
#pragma unroll
    for (int m = 0; m < 16; m++) acc[m] = 0.0f;

    const int2* bk = g_bucket + (size_t)a * CAP;

    // Register-resident bucket: lane j of chunk c holds entry c*32+j.
    int2 b0 = make_int2(0, 0), b1 = b0, b2 = b0;
    if (deg > 0)  b0 = __ldg(bk + min(k, deg - 1));
    if (deg > 32) b1 = __ldg(bk + min(32 + k, deg - 1));
    if (deg > 64) b2 = __ldg(bk + min(64 + k, deg - 1));

    int c0 = deg < 32 ? deg : 32;
    int c1 = deg > 32 ? (deg - 32 < 32 ? deg - 32 : 32) : 0;
    int c2 = deg > 64 ? deg - 64 : 0;
    if (c0) chunk_accum(acc, k, c0, b0, sh, rb, emb);
    if (c1) chunk_accum(acc, k, c1, b1, sh, rb, emb);
    if (c2) chunk_accum(acc, k, c2, b2, sh, rb, emb);

    // Overflow edges for this atom (empty on this dataset: deg max ~60 << CAP).
    if (deg_raw > CAP) {
        int novf = g_ovf_count;
        if (novf > OVF_CAP) novf = OVF_CAP;
        for (int j = 0; j < novf; j++) {
            int e = g_ovf[j];
            if (centers[e] == a) edge_accum(acc, k, sh, rb, emb, e, neighbors[e]);
        }
    }

    float* o = out + (size_t)a * 512 + k;
#pragma unroll
    for (int m = 0; m < 16; m++) o[m * 32] = acc[m] * MP_SCALING;

    // Restore scratch invariant for the next graph replay.
    if (k == 0) g_count[a] = 0;
    if (a == 0 && k == 0) g_ovf_count = 0;
}

extern "C" void kernel_launch(void* const* d_in, const int* in_sizes, int n_in,
                              void* d_out, int out_size) {
    const float* sh        = (const float*)d_in[0];  // (E, 16)
    const float* rb        = (const float*)d_in[1];  // (E, 4, 32)
    const float* emb       = (const float*)d_in[2];  // (n_atoms, 32)
    const int*   centers   = (const int*)d_in[3];    // (E,)
    const int*   neighbors = (const int*)d_in[4];    // (E,)
    float*       out       = (float*)d_out;          // (n_atoms, 16, 32)

    int E       = in_sizes[0] / 16;
    int n_atoms = in_sizes[2] / 32;

    scatter_kernel<<<(E / 2 + 255) / 256, 256>>>(centers, neighbors, E);
    gather_kernel<<<(n_atoms + 3) / 4, 128>>>(sh, rb, emb, centers, neighbors,
                                              out, n_atoms);
}

// round 7
// speedup vs baseline: 1.0666x; 1.0666x over previous
#include <cuda_runtime.h>
#include <cuda_pipeline.h>

// Problem constants (shapes are fixed by the dataset).
#define N_ATOMS_C 20000
#define CAP 96          // per-atom bucket capacity; dataset max degree ~60
#define OVF_CAP 8192
#define MP_SCALING 0.1f
#define GW 8            // warps per gather block

// Scratch: __device__ globals (no allocations allowed; zero-initialized at
// module load). Invariant: g_count/g_ovf_count are 0 on entry to
// kernel_launch and restored to 0 by gather_kernel, so every call does
// identical work.
__device__ int  g_count[N_ATOMS_C];
__device__ int2 g_bucket[N_ATOMS_C * CAP];   // (edge_id, neighbor_id)
__device__ int  g_ovf_count;
__device__ int  g_ovf[OVF_CAP];

__device__ __forceinline__ void scatter_one(int e, int c, int n) {
    int pos = atomicAdd(&g_count[c], 1);
    if (pos < CAP) {
        g_bucket[c * CAP + pos] = make_int2(e, n);
    } else {
        int o = atomicAdd(&g_ovf_count, 1);
        if (o < OVF_CAP) g_ovf[o] = e;
    }
}

__global__ void scatter_kernel(const int* __restrict__ centers,
                               const int* __restrict__ neighbors, int E) {
    int t = blockIdx.x * blockDim.x + threadIdx.x;
    int e = t * 2;
    if (e + 1 < E) {
        int2 c = *(const int2*)(centers + e);
        int2 n = *(const int2*)(neighbors + e);
        scatter_one(e,     c.x, n.x);
        scatter_one(e + 1, c.y, n.y);
    } else if (e < E) {
        scatter_one(e, centers[e], neighbors[e]);
    }
}

// Single-edge accumulate (tail / overflow path), direct LDG.
__device__ __forceinline__ void edge_accum(
    float acc[16], int k,
    const float* __restrict__ sh,
    const float* __restrict__ rb,
    const float* __restrict__ emb,
    int e, int n)
{
    const float* rbe = rb + (size_t)e * 128 + k;
    float r0 = __ldg(rbe), r1 = __ldg(rbe + 32), r2 = __ldg(rbe + 64), r3 = __ldg(rbe + 96);
    float em = __ldg(emb + (size_t)n * 32 + k);
    float sv = (k < 16) ? __ldg(sh + (size_t)e * 16 + k) : 0.0f;
    float t0 = r0 * em, t1 = r1 * em, t2 = r2 * em, t3 = r3 * em;
#pragma unroll
    for (int m = 0; m < 16; m++) {
        float s = __shfl_sync(0xffffffffu, sv, m);
        float t = (m < 1) ? t0 : (m < 4) ? t1 : (m < 9) ? t2 : t3;
        acc[m] = fmaf(s, t, acc[m]);
    }
}

// Stage the rb rows of a 4-edge group into smem: lane k copies bytes
// [k*16, k*16+16) of each 512B row. 4 LDGSTS per warp per group, zero
// register residency for the in-flight data.
__device__ __forceinline__ void stage_rb_group(
    float* dst, const float* __restrict__ rb, int k,
    int e0, int e1, int e2, int e3)
{
    char* d = (char*)dst + k * 16;
    __pipeline_memcpy_async(d,          (const char*)(rb + (size_t)e0 * 128) + k * 16, 16);
    __pipeline_memcpy_async(d + 512,    (const char*)(rb + (size_t)e1 * 128) + k * 16, 16);
    __pipeline_memcpy_async(d + 1024,   (const char*)(rb + (size_t)e2 * 128) + k * 16, 16);
    __pipeline_memcpy_async(d + 1536,   (const char*)(rb + (size_t)e3 * 128) + k * 16, 16);
}

// One warp per atom; lane = k. rb rows for the next 4-edge group stream
// into double-buffered smem via cp.async while the current group computes.
__global__ __launch_bounds__(256) void gather_kernel(
    const float* __restrict__ sh, const float* __restrict__ rb,
    const float* __restrict__ emb,
    const int* __restrict__ centers, const int* __restrict__ neighbors,
    float* __restrict__ out, int n_atoms)
{
    __shared__ float rbbuf[GW][2][4 * 128];   // 32 KB/block

    int wid = threadIdx.x >> 5;
    int k   = threadIdx.x & 31;
    int a   = blockIdx.x * GW + wid;
    if (a >= n_atoms) return;

    int deg_raw = g_count[a];
    int deg = deg_raw > CAP ? CAP : deg_raw;

    float acc[16];
#pragma unroll
    for (int m = 0; m < 16; m++) acc[m] = 0.0f;

    const int2* bk = g_bucket + (size_t)a * CAP;
    int ng = deg >> 2;                        // full 4-edge groups

    int4 bA = make_int4(0,0,0,0), bB = bA, nA = bA, nB = bA;
    if (ng > 0) {
        bA = __ldg((const int4*)bk);          // e0,n0,e1,n1
        bB = __ldg((const int4*)(bk + 2));    // e2,n2,e3,n3
        stage_rb_group(rbbuf[wid][0], rb, k, bA.x, bA.z, bB.x, bB.z);
    }
    __pipeline_commit();

    for (int g = 0; g < ng; g++) {
        // Prefetch group g+1: bucket ids (L2 hit) + async rb staging.
        if (g + 1 < ng) {
            nA = __ldg((const int4*)(bk + 4 * (g + 1)));
            nB = __ldg((const int4*)(bk + 4 * (g + 1) + 2));
            stage_rb_group(rbbuf[wid][(g + 1) & 1], rb, k, nA.x, nA.z, nB.x, nB.z);
        }
        __pipeline_commit();
        __pipeline_wait_prior(1);             // group g's rb is in smem
        __syncwarp();

        // Front-batched direct loads for group g (emb: L2-resident; sh: 1 LDG
        // covers two rows via lane split).
        float em0 = __ldg(emb + (size_t)bA.y * 32 + k);
        float em1 = __ldg(emb + (size_t)bA.w * 32 + k);
        float em2 = __ldg(emb + (size_t)bB.y * 32 + k);
        float em3 = __ldg(emb + (size_t)bB.w * 32 + k);
        float svA = __ldg(sh + ((k < 16) ? (size_t)bA.x * 16 + k
                                         : (size_t)bA.z * 16 + (k - 16)));
        float svB = __ldg(sh + ((k < 16) ? (size_t)bB.x * 16 + k
                                         : (size_t)bB.z * 16 + (k - 16)));

        const float* buf = rbbuf[wid][g & 1];
        // edge 0
        {
            float r0 = buf[k], r1 = buf[32 + k], r2 = buf[64 + k], r3 = buf[96 + k];
            float t0 = r0 * em0, t1 = r1 * em0, t2 = r2 * em0, t3 = r3 * em0;
#pragma unroll
            for (int m = 0; m < 16; m++) {
                float s = __shfl_sync(0xffffffffu, svA, m);
                float t = (m < 1) ? t0 : (m < 4) ? t1 : (m < 9) ? t2 : t3;
                acc[m] = fmaf(s, t, acc[m]);
            }
        }
        // edge 1
        {
            const float* b = buf + 128;
            float r0 = b[k], r1 = b[32 + k], r2 = b[64 + k], r3 = b[96 + k];
            float t0 = r0 * em1, t1 = r1 * em1, t2 = r2 * em1, t3 = r3 * em1;
#pragma unroll
            for (int m = 0; m < 16; m++) {
                float s = __shfl_sync(0xffffffffu, svA, m + 16);
                float t = (m < 1) ? t0 : (m < 4) ? t1 : (m < 9) ? t2 : t3;
                acc[m] = fmaf(s, t, acc[m]);
            }
        }
        // edge 2
        {
            const float* b = buf + 256;
            float r0 = b[k], r1 = b[32 + k], r2 = b[64 + k], r3 = b[96 + k];
            float t0 = r0 * em2, t1 = r1 * em2, t2 = r2 * em2, t3 = r3 * em2;
#pragma unroll
            for (int m = 0; m < 16; m++) {
                float s = __shfl_sync(0xffffffffu, svB, m);
                float t = (m < 1) ? t0 : (m < 4) ? t1 : (m < 9) ? t2 : t3;
                acc[m] = fmaf(s, t, acc[m]);
            }
        }
        // edge 3
        {
            const float* b = buf + 384;
            float r0 = b[k], r1 = b[32 + k], r2 = b[64 + k], r3 = b[96 + k];
            float t0 = r0 * em3, t1 = r1 * em3, t2 = r2 * em3, t3 = r3 * em3;
#pragma unroll
            for (int m = 0; m < 16; m++) {
                float s = __shfl_sync(0xffffffffu, svB, m + 16);
                float t = (m < 1) ? t0 : (m < 4) ? t1 : (m < 9) ? t2 : t3;
                acc[m] = fmaf(s, t, acc[m]);
            }
        }
        bA = nA; bB = nB;
    }

    // Tail edges (deg % 4).
    for (int i = ng * 4; i < deg; i++) {
        int2 en = __ldg(bk + i);
        edge_accum(acc, k, sh, rb, emb, en.x, en.y);
    }

    // Overflow edges for this atom (empty on this dataset: max deg ~60 << CAP).
    if (deg_raw > CAP) {
        int novf = g_ovf_count;
        if (novf > OVF_CAP) novf = OVF_CAP;
        for (int j = 0; j < novf; j++) {
            int e = g_ovf[j];
            if (centers[e] == a) edge_accum(acc, k, sh, rb, emb, e, neighbors[e]);
        }
    }

    float* o = out + (size_t)a * 512 + k;
#pragma unroll
    for (int m = 0; m < 16; m++) o[m * 32] = acc[m] * MP_SCALING;

    // Restore scratch invariant for the next graph replay.
    if (k == 0) g_count[a] = 0;
    if (a == 0 && k == 0) g_ovf_count = 0;
}

extern "C" void kernel_launch(void* const* d_in, const int* in_sizes, int n_in,
                              void* d_out, int out_size) {
    const float* sh        = (const float*)d_in[0];  // (E, 16)
    const float* rb        = (const float*)d_in[1];  // (E, 4, 32)
    const float* emb       = (const float*)d_in[2];  // (n_atoms, 32)
    const int*   centers   = (const int*)d_in[3];    // (E,)
    const int*   neighbors = (const int*)d_in[4];    // (E,)
    float*       out       = (float*)d_out;          // (n_atoms, 16, 32)

    int E       = in_sizes[0] / 16;
    int n_atoms = in_sizes[2] / 32;

    scatter_kernel<<<(E / 2 + 255) / 256, 256>>>(centers, neighbors, E);
    gather_kernel<<<(n_atoms + GW - 1) / GW, 32 * GW>>>(sh, rb, emb, centers,
                                                        neighbors, out, n_atoms);
}